// round 1
// baseline (speedup 1.0000x reference)
#include <cuda_runtime.h>
#include <cstdint>
#include <cstddef>

// ---------------------------------------------------------------------------
// Scratch (device globals -- allocation-free per harness rules)
// ---------------------------------------------------------------------------
#define MAXN 30000
#define MAXE 480000

__device__ float g_h1[MAXN * 640];      // layer-1 features  [N][H*64]
__device__ float g_out1[MAXN * 640];    // layer-1 GAT output
__device__ float g_hsum[MAXN * 64];     // relu+head-sum     [N][64]
__device__ float g_h2[MAXN * 128];      // layer-2 features  [N][128]
__device__ float g_out2[MAXN * 128];    // layer-2 output (relu'd)
__device__ float g_el[MAXN * 10];
__device__ float g_er[MAXN * 10];
__device__ float g_el2[MAXN];
__device__ float g_er2[MAXN];
__device__ int   g_rowptr[MAXN + 1];
__device__ int   g_cursor[MAXN + 1];
__device__ int   g_csrsrc[MAXE];
__device__ float g_read[32 * 256];      // [B][lig 0..127 | rec 128..255]

// ---------------------------------------------------------------------------
// CSR build: histogram -> exclusive scan -> bucket scatter
// ---------------------------------------------------------------------------
__global__ void hist_kernel(const int* __restrict__ dst, int* __restrict__ deg, int E) {
    int i = blockIdx.x * blockDim.x + threadIdx.x;
    if (i < E) atomicAdd(&deg[dst[i]], 1);
}

// single block, 1024 threads; deg (in g_cursor) -> exclusive prefix in
// rowptr AND g_cursor (cursor reused as scatter write-heads).
__global__ void scan_kernel(int* __restrict__ deg_cursor, int* __restrict__ rowptr, int n) {
    __shared__ int sh[1024];
    int t = threadIdx.x;
    int carry = 0;
    for (int base = 0; base < n; base += 1024) {
        int i = base + t;
        int v = (i < n) ? deg_cursor[i] : 0;
        sh[t] = v;
        __syncthreads();
        for (int off = 1; off < 1024; off <<= 1) {
            int tmp = (t >= off) ? sh[t - off] : 0;
            __syncthreads();
            sh[t] += tmp;
            __syncthreads();
        }
        int incl  = sh[t];
        int total = sh[1023];
        if (i < n) {
            int excl = carry + incl - v;
            rowptr[i]     = excl;
            deg_cursor[i] = excl;
        }
        carry += total;
        __syncthreads();
    }
    if (t == 0) rowptr[n] = carry;
}

__global__ void scatter_kernel(const int* __restrict__ src, const int* __restrict__ dst,
                               int* __restrict__ cursor, int* __restrict__ csrsrc, int E) {
    int i = blockIdx.x * blockDim.x + threadIdx.x;
    if (i < E) {
        int p = atomicAdd(&cursor[dst[i]], 1);
        csrsrc[p] = src[i];
    }
}

// ---------------------------------------------------------------------------
// GEMM: C[N,P] = X[N,64] @ W[64,P]   (P multiple of 64; K=64 fits one tile)
// 64x64 tile, 256 threads, 4x4 register micro-tile, float4 smem reads.
// ---------------------------------------------------------------------------
__global__ void gemm_xw(const float* __restrict__ X, const float* __restrict__ W,
                        float* __restrict__ C, int N, int P) {
    __shared__ float XsT[64][68];   // [k][row], padded (16B-aligned rows, few store conflicts)
    __shared__ float Ws[64][64];    // [k][col]

    const int bm  = blockIdx.y * 64;
    const int bn  = blockIdx.x * 64;
    const int tid = threadIdx.x;

#pragma unroll
    for (int i = 0; i < 16; i++) {
        int e = tid + i * 256;
        int r = e >> 6, k = e & 63;
        XsT[k][r] = (bm + r < N) ? X[(size_t)(bm + r) * 64 + k] : 0.f;
    }
#pragma unroll
    for (int i = 0; i < 16; i++) {
        int e = tid + i * 256;
        int k = e >> 6, c = e & 63;
        Ws[k][c] = W[(size_t)k * P + bn + c];
    }
    __syncthreads();

    const int tx = tid & 15, ty = tid >> 4;
    const int r0 = ty * 4, c0 = tx * 4;
    float acc[4][4] = {};

#pragma unroll
    for (int k = 0; k < 64; k++) {
        float4 a = *reinterpret_cast<const float4*>(&XsT[k][r0]);
        float4 b = *reinterpret_cast<const float4*>(&Ws[k][c0]);
        acc[0][0] += a.x * b.x; acc[0][1] += a.x * b.y; acc[0][2] += a.x * b.z; acc[0][3] += a.x * b.w;
        acc[1][0] += a.y * b.x; acc[1][1] += a.y * b.y; acc[1][2] += a.y * b.z; acc[1][3] += a.y * b.w;
        acc[2][0] += a.z * b.x; acc[2][1] += a.z * b.y; acc[2][2] += a.z * b.z; acc[2][3] += a.z * b.w;
        acc[3][0] += a.w * b.x; acc[3][1] += a.w * b.y; acc[3][2] += a.w * b.z; acc[3][3] += a.w * b.w;
    }

#pragma unroll
    for (int i = 0; i < 4; i++) {
        int r = bm + r0 + i;
        if (r < N) {
            float4 v = make_float4(acc[i][0], acc[i][1], acc[i][2], acc[i][3]);
            *reinterpret_cast<float4*>(&C[(size_t)r * P + bn + c0]) = v;
        }
    }
}

// ---------------------------------------------------------------------------
// Per-(node, head) attention logits: el = <h, al>, er = <h, ar>. Warp each.
// ---------------------------------------------------------------------------
__global__ void elr_kernel(const float* __restrict__ h, const float* __restrict__ al,
                           const float* __restrict__ ar, float* __restrict__ el,
                           float* __restrict__ er, int N, int H, int D) {
    int gw   = (blockIdx.x * blockDim.x + threadIdx.x) >> 5;
    int lane = threadIdx.x & 31;
    if (gw >= N * H) return;
    int n = gw / H, hh = gw - n * H;
    const float* hp  = h + (size_t)n * H * D + (size_t)hh * D;
    const float* alp = al + hh * D;
    const float* arp = ar + hh * D;
    float sl = 0.f, sr = 0.f;
    for (int d = lane; d < D; d += 32) {
        float v = hp[d];
        sl += v * alp[d];
        sr += v * arp[d];
    }
#pragma unroll
    for (int o = 16; o; o >>= 1) {
        sl += __shfl_xor_sync(0xffffffffu, sl, o);
        sr += __shfl_xor_sync(0xffffffffu, sr, o);
    }
    if (lane == 0) { el[gw] = sl; er[gw] = sr; }
}

__device__ __forceinline__ float lrelu02(float e) { return fmaxf(e, 0.2f * e); }

// ---------------------------------------------------------------------------
// Layer-1 gather (D=64): warp per (dst node, head). Fused edge-softmax:
// pass 1 lane-parallel max; pass 2 serial weighted accumulate; divide once.
// ---------------------------------------------------------------------------
__global__ void gather64_kernel(const float* __restrict__ h, const int* __restrict__ rowptr,
                                const int* __restrict__ csrsrc, const float* __restrict__ el,
                                const float* __restrict__ er, float* __restrict__ out,
                                int N, int H) {
    int gw   = (blockIdx.x * blockDim.x + threadIdx.x) >> 5;
    int lane = threadIdx.x & 31;
    if (gw >= N * H) return;
    int n = gw / H, hh = gw - n * H;
    int beg = rowptr[n], end = rowptr[n + 1];
    size_t obase = (size_t)gw * 64;
    if (beg == end) {                 // no incoming edges -> zero message
        out[obase + lane] = 0.f;
        out[obase + lane + 32] = 0.f;
        return;
    }
    float ern = er[gw];
    float m = -1e30f;
    for (int i = beg + lane; i < end; i += 32) {
        float e = lrelu02(el[(size_t)csrsrc[i] * H + hh] + ern);
        m = fmaxf(m, e);
    }
#pragma unroll
    for (int o = 16; o; o >>= 1) m = fmaxf(m, __shfl_xor_sync(0xffffffffu, m, o));

    float a0 = 0.f, a1 = 0.f, den = 0.f;
    for (int i = beg; i < end; i++) {
        int s = csrsrc[i];
        float e = lrelu02(el[(size_t)s * H + hh] + ern);
        float w = __expf(e - m);
        den += w;
        const float* hp = h + ((size_t)s * H + hh) * 64;
        a0 += w * hp[lane];
        a1 += w * hp[lane + 32];
    }
    float inv = 1.0f / den;
    out[obase + lane]      = a0 * inv;
    out[obase + lane + 32] = a1 * inv;
}

// ---------------------------------------------------------------------------
// relu(out1 + b1) summed over 10 heads -> [N,64]
// ---------------------------------------------------------------------------
__global__ void sumheads_kernel(const float* __restrict__ out1, const float* __restrict__ b1,
                                float* __restrict__ hsum, int N) {
    int i = blockIdx.x * blockDim.x + threadIdx.x;
    if (i >= N * 64) return;
    int n = i >> 6, d = i & 63;
    float s = 0.f;
#pragma unroll
    for (int hh = 0; hh < 10; hh++) {
        float v = out1[(size_t)n * 640 + hh * 64 + d] + b1[hh * 64 + d];
        s += fmaxf(v, 0.f);
    }
    hsum[i] = s;
}

// ---------------------------------------------------------------------------
// Layer-2 gather (H=1, D=128), fused bias + relu. Warp per dst node.
// ---------------------------------------------------------------------------
__global__ void gather128_kernel(const float* __restrict__ h2, const int* __restrict__ rowptr,
                                 const int* __restrict__ csrsrc, const float* __restrict__ el,
                                 const float* __restrict__ er, const float* __restrict__ b2,
                                 float* __restrict__ out, int N) {
    int gw   = (blockIdx.x * blockDim.x + threadIdx.x) >> 5;
    int lane = threadIdx.x & 31;
    if (gw >= N) return;
    int beg = rowptr[gw], end = rowptr[gw + 1];
    float a[4] = {0.f, 0.f, 0.f, 0.f};
    float den = 1.f;
    if (beg < end) {
        den = 0.f;
        float ern = er[gw];
        float m = -1e30f;
        for (int i = beg + lane; i < end; i += 32) {
            float e = lrelu02(el[csrsrc[i]] + ern);
            m = fmaxf(m, e);
        }
#pragma unroll
        for (int o = 16; o; o >>= 1) m = fmaxf(m, __shfl_xor_sync(0xffffffffu, m, o));
        for (int i = beg; i < end; i++) {
            int s = csrsrc[i];
            float e = lrelu02(el[s] + ern);
            float w = __expf(e - m);
            den += w;
            const float* hp = h2 + (size_t)s * 128;
#pragma unroll
            for (int j = 0; j < 4; j++) a[j] += w * hp[lane + 32 * j];
        }
    }
    float inv = 1.0f / den;
#pragma unroll
    for (int j = 0; j < 4; j++) {
        int d = lane + 32 * j;
        out[(size_t)gw * 128 + d] = fmaxf(a[j] * inv + b2[d], 0.f);
    }
}

// ---------------------------------------------------------------------------
// Graph-max readout: values >= 0 (post-relu), so int-punned atomicMax is exact.
// ---------------------------------------------------------------------------
__global__ void readout_kernel(const float* __restrict__ out2, const int* __restrict__ gid,
                               float* __restrict__ read, int N, int off) {
    int i = blockIdx.x * blockDim.x + threadIdx.x;
    if (i >= N * 128) return;
    int n = i >> 7, d = i & 127;
    float v = out2[i];
    atomicMax(reinterpret_cast<int*>(read) + (size_t)gid[n] * 256 + off + d,
              __float_as_int(v));
}

// ---------------------------------------------------------------------------
// Final MLP head: [32,256] -> relu(@W1+b1) -> relu(@W2+b2) -> [32]
// ---------------------------------------------------------------------------
__global__ void mlp_kernel(const float* __restrict__ read, const float* __restrict__ W1,
                           const float* __restrict__ bb1, const float* __restrict__ W2,
                           const float* __restrict__ bb2, float* __restrict__ out) {
    __shared__ float sin[256];
    __shared__ float red[128];
    int t = threadIdx.x;   // 128 threads
    for (int b = 0; b < 32; b++) {
        sin[t]       = read[b * 256 + t];
        sin[t + 128] = read[b * 256 + 128 + t];
        __syncthreads();
        float acc = bb1[t];
#pragma unroll 4
        for (int k = 0; k < 256; k++) acc += sin[k] * W1[(size_t)k * 128 + t];
        acc = fmaxf(acc, 0.f);
        red[t] = acc * W2[t];
        __syncthreads();
        for (int o = 64; o; o >>= 1) {
            if (t < o) red[t] += red[t + o];
            __syncthreads();
        }
        if (t == 0) out[b] = fmaxf(red[0] + bb2[0], 0.f);
        __syncthreads();
    }
}

// ---------------------------------------------------------------------------
// Host-side orchestration
// ---------------------------------------------------------------------------
static inline int div_up(int a, int b) { return (a + b - 1) / b; }

struct Scratch {
    float *h1, *out1, *hsum, *h2, *out2, *el, *er, *el2, *er2, *read;
    int *rowptr, *cursor, *csrsrc;
};

static void run_branch(const Scratch& S,
                       const float* x, const int* src, const int* dst, const int* gid,
                       const float* W1, const float* al1, const float* ar1, const float* b1,
                       const float* W2, const float* al2, const float* ar2, const float* b2,
                       int N, int E, int off) {
    // ---- CSR by dst ----
    cudaMemsetAsync(S.cursor, 0, sizeof(int) * (size_t)N, 0);
    hist_kernel<<<div_up(E, 256), 256>>>(dst, S.cursor, E);
    scan_kernel<<<1, 1024>>>(S.cursor, S.rowptr, N);
    scatter_kernel<<<div_up(E, 256), 256>>>(src, dst, S.cursor, S.csrsrc, E);

    // ---- layer 1 (H=10, D=64) ----
    gemm_xw<<<dim3(640 / 64, div_up(N, 64)), 256>>>(x, W1, S.h1, N, 640);
    {
        int warps = N * 10;
        elr_kernel<<<div_up(warps * 32, 256), 256>>>(S.h1, al1, ar1, S.el, S.er, N, 10, 64);
        gather64_kernel<<<div_up(warps * 32, 256), 256>>>(S.h1, S.rowptr, S.csrsrc,
                                                          S.el, S.er, S.out1, N, 10);
    }
    sumheads_kernel<<<div_up(N * 64, 256), 256>>>(S.out1, b1, S.hsum, N);

    // ---- layer 2 (H=1, D=128) ----
    gemm_xw<<<dim3(128 / 64, div_up(N, 64)), 256>>>(S.hsum, W2, S.h2, N, 128);
    elr_kernel<<<div_up(N * 32, 256), 256>>>(S.h2, al2, ar2, S.el2, S.er2, N, 1, 128);
    gather128_kernel<<<div_up(N * 32, 256), 256>>>(S.h2, S.rowptr, S.csrsrc,
                                                   S.el2, S.er2, b2, S.out2, N);

    // ---- graph-max readout ----
    readout_kernel<<<div_up(N * 128, 256), 256>>>(S.out2, gid, S.read, N, off);
}

extern "C" void kernel_launch(void* const* d_in, const int* in_sizes, int n_in,
                              void* d_out, int out_size) {
    (void)n_in; (void)out_size;
    const float* x_lig   = (const float*)d_in[0];
    const int*   src_lig = (const int*)  d_in[1];
    const int*   dst_lig = (const int*)  d_in[2];
    const int*   gid_lig = (const int*)  d_in[3];
    const float* x_rec   = (const float*)d_in[4];
    const int*   src_rec = (const int*)  d_in[5];
    const int*   dst_rec = (const int*)  d_in[6];
    const int*   gid_rec = (const int*)  d_in[7];
    const float* W1l  = (const float*)d_in[8];
    const float* al1l = (const float*)d_in[9];
    const float* ar1l = (const float*)d_in[10];
    const float* b1l  = (const float*)d_in[11];
    const float* W2l  = (const float*)d_in[12];
    const float* al2l = (const float*)d_in[13];
    const float* ar2l = (const float*)d_in[14];
    const float* b2l  = (const float*)d_in[15];
    const float* W1r  = (const float*)d_in[16];
    const float* al1r = (const float*)d_in[17];
    const float* ar1r = (const float*)d_in[18];
    const float* b1r  = (const float*)d_in[19];
    const float* W2r  = (const float*)d_in[20];
    const float* al2r = (const float*)d_in[21];
    const float* ar2r = (const float*)d_in[22];
    const float* b2r  = (const float*)d_in[23];
    const float* W_lin1 = (const float*)d_in[24];
    const float* b_lin1 = (const float*)d_in[25];
    const float* W_lin2 = (const float*)d_in[26];
    const float* b_lin2 = (const float*)d_in[27];

    const int N_l = in_sizes[0] / 64;
    const int E_l = in_sizes[1];
    const int N_r = in_sizes[4] / 64;
    const int E_r = in_sizes[5];

    Scratch S;
    cudaGetSymbolAddress((void**)&S.h1,     g_h1);
    cudaGetSymbolAddress((void**)&S.out1,   g_out1);
    cudaGetSymbolAddress((void**)&S.hsum,   g_hsum);
    cudaGetSymbolAddress((void**)&S.h2,     g_h2);
    cudaGetSymbolAddress((void**)&S.out2,   g_out2);
    cudaGetSymbolAddress((void**)&S.el,     g_el);
    cudaGetSymbolAddress((void**)&S.er,     g_er);
    cudaGetSymbolAddress((void**)&S.el2,    g_el2);
    cudaGetSymbolAddress((void**)&S.er2,    g_er2);
    cudaGetSymbolAddress((void**)&S.rowptr, g_rowptr);
    cudaGetSymbolAddress((void**)&S.cursor, g_cursor);
    cudaGetSymbolAddress((void**)&S.csrsrc, g_csrsrc);
    cudaGetSymbolAddress((void**)&S.read,   g_read);

    cudaMemsetAsync(S.read, 0, sizeof(float) * 32 * 256, 0);

    run_branch(S, x_lig, src_lig, dst_lig, gid_lig,
               W1l, al1l, ar1l, b1l, W2l, al2l, ar2l, b2l, N_l, E_l, 0);
    run_branch(S, x_rec, src_rec, dst_rec, gid_rec,
               W1r, al1r, ar1r, b1r, W2r, al2r, ar2r, b2r, N_r, E_r, 128);

    mlp_kernel<<<1, 128>>>(S.read, W_lin1, b_lin1, W_lin2, b_lin2, (float*)d_out);
}

// round 2
// speedup vs baseline: 1.3885x; 1.3885x over previous
#include <cuda_runtime.h>
#include <cstdint>
#include <cstddef>

// ---------------------------------------------------------------------------
// Scratch (device globals -- allocation-free per harness rules)
// ---------------------------------------------------------------------------
#define MAXN 30000
#define MAXE 480000

__device__ float g_h1[MAXN * 640];      // layer-1 features  [N][H*64]
__device__ float g_hsum[MAXN * 64];     // relu+head-sum     [N][64]
__device__ float g_h2[MAXN * 128];      // layer-2 features  [N][128]
__device__ float g_el[MAXN * 10];
__device__ float g_er[MAXN * 10];
__device__ float g_el2[MAXN];
__device__ float g_er2[MAXN];
__device__ int   g_rowptr[MAXN + 1];
__device__ int   g_cursor[MAXN + 1];
__device__ int   g_csrsrc[MAXE];
__device__ float g_read[32 * 256];      // [B][lig 0..127 | rec 128..255]

__device__ __forceinline__ float lrelu02(float e) { return fmaxf(e, 0.2f * e); }

// ---------------------------------------------------------------------------
// CSR build: histogram -> shfl-based exclusive scan -> bucket scatter
// ---------------------------------------------------------------------------
__global__ void hist_kernel(const int* __restrict__ dst, int* __restrict__ deg, int E) {
    int i = blockIdx.x * blockDim.x + threadIdx.x;
    if (i < E) atomicAdd(&deg[dst[i]], 1);
}

// single block, 1024 threads (32 warps); counts in dc -> exclusive prefix in
// rowptr AND dc (dc reused as scatter write-heads).
__global__ void scan_kernel(int* __restrict__ dc, int* __restrict__ rowptr, int n) {
    __shared__ int wsum[32];
    __shared__ int carry_sh;
    int t = threadIdx.x, lane = t & 31, w = t >> 5;
    if (t == 0) carry_sh = 0;
    __syncthreads();
    for (int base = 0; base < n; base += 1024) {
        int i = base + t;
        int v = (i < n) ? dc[i] : 0;
        int x = v;
#pragma unroll
        for (int o = 1; o < 32; o <<= 1) {
            int y = __shfl_up_sync(0xffffffffu, x, o);
            if (lane >= o) x += y;
        }
        if (lane == 31) wsum[w] = x;
        __syncthreads();
        if (w == 0) {
            int s = wsum[lane];
#pragma unroll
            for (int o = 1; o < 32; o <<= 1) {
                int y = __shfl_up_sync(0xffffffffu, s, o);
                if (lane >= o) s += y;
            }
            wsum[lane] = s;           // inclusive scan of warp totals
        }
        __syncthreads();
        int carry = carry_sh;
        int excl = carry + (w ? wsum[w - 1] : 0) + (x - v);
        if (i < n) { rowptr[i] = excl; dc[i] = excl; }
        __syncthreads();              // all have read carry_sh / wsum
        if (t == 0) carry_sh = carry + wsum[31];
        __syncthreads();
    }
    if (threadIdx.x == 0) rowptr[n] = carry_sh;
}

__global__ void scatter_kernel(const int* __restrict__ src, const int* __restrict__ dst,
                               int* __restrict__ cursor, int* __restrict__ csrsrc, int E) {
    int i = blockIdx.x * blockDim.x + threadIdx.x;
    if (i < E) {
        int p = atomicAdd(&cursor[dst[i]], 1);
        csrsrc[p] = src[i];
    }
}

// ---------------------------------------------------------------------------
// GEMM: C[N,P] = X[N,64] @ W[64,P]   (P multiple of 64; K=64 one tile)
// 64x64 tile, 256 threads, 4x4 micro-tile. When FUSE_ELR: each col-tile is
// exactly one head (P=640), epilogue computes el/er = <h_row, al/ar> with an
// in-warp shfl reduction (deterministic, no atomics).
// ---------------------------------------------------------------------------
template <bool FUSE_ELR>
__global__ void gemm_xw(const float* __restrict__ X, const float* __restrict__ W,
                        float* __restrict__ C, int N, int P,
                        const float* __restrict__ alf, const float* __restrict__ arf,
                        float* __restrict__ el, float* __restrict__ er) {
    __shared__ float XsT[64][68];
    __shared__ float Ws[64][64];

    const int bm  = blockIdx.y * 64;
    const int bn  = blockIdx.x * 64;
    const int tid = threadIdx.x;

#pragma unroll
    for (int i = 0; i < 16; i++) {
        int e = tid + i * 256;
        int r = e >> 6, k = e & 63;
        XsT[k][r] = (bm + r < N) ? X[(size_t)(bm + r) * 64 + k] : 0.f;
    }
#pragma unroll
    for (int i = 0; i < 16; i++) {
        int e = tid + i * 256;
        int k = e >> 6, c = e & 63;
        Ws[k][c] = W[(size_t)k * P + bn + c];
    }
    __syncthreads();

    const int tx = tid & 15, ty = tid >> 4;
    const int r0 = ty * 4, c0 = tx * 4;
    float acc[4][4] = {};

#pragma unroll
    for (int k = 0; k < 64; k++) {
        float4 a = *reinterpret_cast<const float4*>(&XsT[k][r0]);
        float4 b = *reinterpret_cast<const float4*>(&Ws[k][c0]);
        acc[0][0] += a.x * b.x; acc[0][1] += a.x * b.y; acc[0][2] += a.x * b.z; acc[0][3] += a.x * b.w;
        acc[1][0] += a.y * b.x; acc[1][1] += a.y * b.y; acc[1][2] += a.y * b.z; acc[1][3] += a.y * b.w;
        acc[2][0] += a.z * b.x; acc[2][1] += a.z * b.y; acc[2][2] += a.z * b.z; acc[2][3] += a.z * b.w;
        acc[3][0] += a.w * b.x; acc[3][1] += a.w * b.y; acc[3][2] += a.w * b.z; acc[3][3] += a.w * b.w;
    }

#pragma unroll
    for (int i = 0; i < 4; i++) {
        int r = bm + r0 + i;
        if (r < N) {
            float4 v = make_float4(acc[i][0], acc[i][1], acc[i][2], acc[i][3]);
            *reinterpret_cast<float4*>(&C[(size_t)r * P + bn + c0]) = v;
        }
    }

    if (FUSE_ELR) {
        float av[4], rv[4];
        *reinterpret_cast<float4*>(av) = *reinterpret_cast<const float4*>(&alf[bn + c0]);
        *reinterpret_cast<float4*>(rv) = *reinterpret_cast<const float4*>(&arf[bn + c0]);
        const int h = bn >> 6;
#pragma unroll
        for (int i = 0; i < 4; i++) {
            float pl = acc[i][0] * av[0] + acc[i][1] * av[1] + acc[i][2] * av[2] + acc[i][3] * av[3];
            float pr = acc[i][0] * rv[0] + acc[i][1] * rv[1] + acc[i][2] * rv[2] + acc[i][3] * rv[3];
#pragma unroll
            for (int o = 1; o < 16; o <<= 1) {
                pl += __shfl_xor_sync(0xffffffffu, pl, o);
                pr += __shfl_xor_sync(0xffffffffu, pr, o);
            }
            if (tx == 0) {
                int r = bm + r0 + i;
                if (r < N) {
                    el[(size_t)r * 10 + h] = pl;
                    er[(size_t)r * 10 + h] = pr;
                }
            }
        }
    }
}

// ---------------------------------------------------------------------------
// Layer-2 attention logits (H=1, D=128): warp per node.
// ---------------------------------------------------------------------------
__global__ void elr2_kernel(const float* __restrict__ h, const float* __restrict__ al,
                            const float* __restrict__ ar, float* __restrict__ el,
                            float* __restrict__ er, int N) {
    int gw   = (blockIdx.x * blockDim.x + threadIdx.x) >> 5;
    int lane = threadIdx.x & 31;
    if (gw >= N) return;
    const float4 v0 = *reinterpret_cast<const float4*>(h + (size_t)gw * 128 + lane * 4);
    const float4 a0 = *reinterpret_cast<const float4*>(al + lane * 4);
    const float4 r0 = *reinterpret_cast<const float4*>(ar + lane * 4);
    float sl = v0.x * a0.x + v0.y * a0.y + v0.z * a0.z + v0.w * a0.w;
    float sr = v0.x * r0.x + v0.y * r0.y + v0.z * r0.z + v0.w * r0.w;
#pragma unroll
    for (int o = 16; o; o >>= 1) {
        sl += __shfl_xor_sync(0xffffffffu, sl, o);
        sr += __shfl_xor_sync(0xffffffffu, sr, o);
    }
    if (lane == 0) { el[gw] = sl; er[gw] = sr; }
}

// ---------------------------------------------------------------------------
// Layer-1 fused gather: block per dst node, 160 threads (5 warps, 2 heads per
// warp via float4; 16 lanes cover one head's 64 dims). Fused edge-softmax
// (no-max form, clamped), bias, relu, and head-sum -> hsum[n][64].
// ---------------------------------------------------------------------------
__global__ void gat1_gather(const float* __restrict__ h1, const int* __restrict__ rowptr,
                            const int* __restrict__ csrsrc, const float* __restrict__ el,
                            const float* __restrict__ er, const float* __restrict__ b1,
                            float* __restrict__ hsum) {
    __shared__ float hs[5][64];
    const int n    = blockIdx.x;
    const int t    = threadIdx.x;
    const int w    = t >> 5, lane = t & 31;
    const int hd   = 2 * w + (lane >> 4);
    const int db   = (lane & 15) * 4;
    const int beg  = rowptr[n], end = rowptr[n + 1];

    float4 acc = make_float4(0.f, 0.f, 0.f, 0.f);
    float den = 1.f;
    if (beg < end) {
        den = 0.f;
        const float ern = er[(size_t)n * 10 + hd];
        int i = beg;
        for (; i + 2 <= end; i += 2) {
            int s0 = csrsrc[i], s1 = csrsrc[i + 1];
            float e0 = el[(size_t)s0 * 10 + hd];
            float e1 = el[(size_t)s1 * 10 + hd];
            float4 v0 = *reinterpret_cast<const float4*>(h1 + (size_t)s0 * 640 + hd * 64 + db);
            float4 v1 = *reinterpret_cast<const float4*>(h1 + (size_t)s1 * 640 + hd * 64 + db);
            float w0 = __expf(fminf(lrelu02(e0 + ern), 60.f));
            float w1 = __expf(fminf(lrelu02(e1 + ern), 60.f));
            den += w0 + w1;
            acc.x += w0 * v0.x + w1 * v1.x;
            acc.y += w0 * v0.y + w1 * v1.y;
            acc.z += w0 * v0.z + w1 * v1.z;
            acc.w += w0 * v0.w + w1 * v1.w;
        }
        if (i < end) {
            int s0 = csrsrc[i];
            float e0 = el[(size_t)s0 * 10 + hd];
            float4 v0 = *reinterpret_cast<const float4*>(h1 + (size_t)s0 * 640 + hd * 64 + db);
            float w0 = __expf(fminf(lrelu02(e0 + ern), 60.f));
            den += w0;
            acc.x += w0 * v0.x; acc.y += w0 * v0.y; acc.z += w0 * v0.z; acc.w += w0 * v0.w;
        }
    }
    const float inv = 1.f / den;
    const float4 bb = *reinterpret_cast<const float4*>(b1 + hd * 64 + db);
    float4 o;
    o.x = fmaxf(acc.x * inv + bb.x, 0.f);
    o.y = fmaxf(acc.y * inv + bb.y, 0.f);
    o.z = fmaxf(acc.z * inv + bb.z, 0.f);
    o.w = fmaxf(acc.w * inv + bb.w, 0.f);
    // sum this warp's two heads (xor 16 pairs identical dims)
    o.x += __shfl_xor_sync(0xffffffffu, o.x, 16);
    o.y += __shfl_xor_sync(0xffffffffu, o.y, 16);
    o.z += __shfl_xor_sync(0xffffffffu, o.z, 16);
    o.w += __shfl_xor_sync(0xffffffffu, o.w, 16);
    if (lane < 16) *reinterpret_cast<float4*>(&hs[w][db]) = o;
    __syncthreads();
    if (t < 64) {
        float s = hs[0][t] + hs[1][t] + hs[2][t] + hs[3][t] + hs[4][t];
        hsum[(size_t)n * 64 + t] = s;
    }
}

// ---------------------------------------------------------------------------
// Layer-2 fused gather + bias + relu + graph-max readout. Warp per dst node;
// one LDG.128 per lane covers all 128 dims. Weights uniform across the warp.
// ---------------------------------------------------------------------------
__global__ void gat2_gather(const float* __restrict__ h2, const int* __restrict__ rowptr,
                            const int* __restrict__ csrsrc, const float* __restrict__ el,
                            const float* __restrict__ er, const float* __restrict__ b2,
                            const int* __restrict__ gid, float* __restrict__ read,
                            int N, int off) {
    int gw   = (blockIdx.x * blockDim.x + threadIdx.x) >> 5;
    int lane = threadIdx.x & 31;
    if (gw >= N) return;
    int beg = rowptr[gw], end = rowptr[gw + 1];
    float4 acc = make_float4(0.f, 0.f, 0.f, 0.f);
    float den = 1.f;
    if (beg < end) {
        den = 0.f;
        const float ern = er[gw];
        int i = beg;
        for (; i + 2 <= end; i += 2) {
            int s0 = csrsrc[i], s1 = csrsrc[i + 1];
            float e0 = el[s0], e1 = el[s1];
            float4 v0 = *reinterpret_cast<const float4*>(h2 + (size_t)s0 * 128 + lane * 4);
            float4 v1 = *reinterpret_cast<const float4*>(h2 + (size_t)s1 * 128 + lane * 4);
            float w0 = __expf(fminf(lrelu02(e0 + ern), 60.f));
            float w1 = __expf(fminf(lrelu02(e1 + ern), 60.f));
            den += w0 + w1;
            acc.x += w0 * v0.x + w1 * v1.x;
            acc.y += w0 * v0.y + w1 * v1.y;
            acc.z += w0 * v0.z + w1 * v1.z;
            acc.w += w0 * v0.w + w1 * v1.w;
        }
        if (i < end) {
            int s0 = csrsrc[i];
            float e0 = el[s0];
            float4 v0 = *reinterpret_cast<const float4*>(h2 + (size_t)s0 * 128 + lane * 4);
            float w0 = __expf(fminf(lrelu02(e0 + ern), 60.f));
            den += w0;
            acc.x += w0 * v0.x; acc.y += w0 * v0.y; acc.z += w0 * v0.z; acc.w += w0 * v0.w;
        }
    }
    const float inv = 1.f / den;
    const float4 bb = *reinterpret_cast<const float4*>(b2 + lane * 4);
    int* rp = reinterpret_cast<int*>(read) + (size_t)gid[gw] * 256 + off + lane * 4;
    atomicMax(rp + 0, __float_as_int(fmaxf(acc.x * inv + bb.x, 0.f)));
    atomicMax(rp + 1, __float_as_int(fmaxf(acc.y * inv + bb.y, 0.f)));
    atomicMax(rp + 2, __float_as_int(fmaxf(acc.z * inv + bb.z, 0.f)));
    atomicMax(rp + 3, __float_as_int(fmaxf(acc.w * inv + bb.w, 0.f)));
}

// ---------------------------------------------------------------------------
// Final MLP head: [32,256] -> relu(@W1+b1) -> relu(@W2+b2) -> [32]
// ---------------------------------------------------------------------------
__global__ void mlp_kernel(const float* __restrict__ read, const float* __restrict__ W1,
                           const float* __restrict__ bb1, const float* __restrict__ W2,
                           const float* __restrict__ bb2, float* __restrict__ out) {
    __shared__ float sin[256];
    __shared__ float red[128];
    int t = threadIdx.x;   // 128 threads
    for (int b = 0; b < 32; b++) {
        sin[t]       = read[b * 256 + t];
        sin[t + 128] = read[b * 256 + 128 + t];
        __syncthreads();
        float acc = bb1[t];
#pragma unroll 4
        for (int k = 0; k < 256; k++) acc += sin[k] * W1[(size_t)k * 128 + t];
        acc = fmaxf(acc, 0.f);
        red[t] = acc * W2[t];
        __syncthreads();
        for (int o = 64; o; o >>= 1) {
            if (t < o) red[t] += red[t + o];
            __syncthreads();
        }
        if (t == 0) out[b] = fmaxf(red[0] + bb2[0], 0.f);
        __syncthreads();
    }
}

// ---------------------------------------------------------------------------
// Host-side orchestration
// ---------------------------------------------------------------------------
static inline int div_up(int a, int b) { return (a + b - 1) / b; }

struct Scratch {
    float *h1, *hsum, *h2, *el, *er, *el2, *er2, *read;
    int *rowptr, *cursor, *csrsrc;
};

static void run_branch(const Scratch& S,
                       const float* x, const int* src, const int* dst, const int* gid,
                       const float* W1, const float* al1, const float* ar1, const float* b1,
                       const float* W2, const float* al2, const float* ar2, const float* b2,
                       int N, int E, int off) {
    // ---- CSR by dst ----
    cudaMemsetAsync(S.cursor, 0, sizeof(int) * (size_t)N, 0);
    hist_kernel<<<div_up(E, 256), 256>>>(dst, S.cursor, E);
    scan_kernel<<<1, 1024>>>(S.cursor, S.rowptr, N);
    scatter_kernel<<<div_up(E, 256), 256>>>(src, dst, S.cursor, S.csrsrc, E);

    // ---- layer 1 (H=10, D=64): GEMM + fused el/er, then fused gather ----
    gemm_xw<true><<<dim3(10, div_up(N, 64)), 256>>>(x, W1, S.h1, N, 640,
                                                    al1, ar1, S.el, S.er);
    gat1_gather<<<N, 160>>>(S.h1, S.rowptr, S.csrsrc, S.el, S.er, b1, S.hsum);

    // ---- layer 2 (H=1, D=128) ----
    gemm_xw<false><<<dim3(2, div_up(N, 64)), 256>>>(S.hsum, W2, S.h2, N, 128,
                                                    nullptr, nullptr, nullptr, nullptr);
    elr2_kernel<<<div_up(N * 32, 256), 256>>>(S.h2, al2, ar2, S.el2, S.er2, N);
    gat2_gather<<<div_up(N * 32, 256), 256>>>(S.h2, S.rowptr, S.csrsrc,
                                              S.el2, S.er2, b2, gid, S.read, N, off);
}

extern "C" void kernel_launch(void* const* d_in, const int* in_sizes, int n_in,
                              void* d_out, int out_size) {
    (void)n_in; (void)out_size;
    const float* x_lig   = (const float*)d_in[0];
    const int*   src_lig = (const int*)  d_in[1];
    const int*   dst_lig = (const int*)  d_in[2];
    const int*   gid_lig = (const int*)  d_in[3];
    const float* x_rec   = (const float*)d_in[4];
    const int*   src_rec = (const int*)  d_in[5];
    const int*   dst_rec = (const int*)  d_in[6];
    const int*   gid_rec = (const int*)  d_in[7];
    const float* W1l  = (const float*)d_in[8];
    const float* al1l = (const float*)d_in[9];
    const float* ar1l = (const float*)d_in[10];
    const float* b1l  = (const float*)d_in[11];
    const float* W2l  = (const float*)d_in[12];
    const float* al2l = (const float*)d_in[13];
    const float* ar2l = (const float*)d_in[14];
    const float* b2l  = (const float*)d_in[15];
    const float* W1r  = (const float*)d_in[16];
    const float* al1r = (const float*)d_in[17];
    const float* ar1r = (const float*)d_in[18];
    const float* b1r  = (const float*)d_in[19];
    const float* W2r  = (const float*)d_in[20];
    const float* al2r = (const float*)d_in[21];
    const float* ar2r = (const float*)d_in[22];
    const float* b2r  = (const float*)d_in[23];
    const float* W_lin1 = (const float*)d_in[24];
    const float* b_lin1 = (const float*)d_in[25];
    const float* W_lin2 = (const float*)d_in[26];
    const float* b_lin2 = (const float*)d_in[27];

    const int N_l = in_sizes[0] / 64;
    const int E_l = in_sizes[1];
    const int N_r = in_sizes[4] / 64;
    const int E_r = in_sizes[5];

    Scratch S;
    cudaGetSymbolAddress((void**)&S.h1,     g_h1);
    cudaGetSymbolAddress((void**)&S.hsum,   g_hsum);
    cudaGetSymbolAddress((void**)&S.h2,     g_h2);
    cudaGetSymbolAddress((void**)&S.el,     g_el);
    cudaGetSymbolAddress((void**)&S.er,     g_er);
    cudaGetSymbolAddress((void**)&S.el2,    g_el2);
    cudaGetSymbolAddress((void**)&S.er2,    g_er2);
    cudaGetSymbolAddress((void**)&S.rowptr, g_rowptr);
    cudaGetSymbolAddress((void**)&S.cursor, g_cursor);
    cudaGetSymbolAddress((void**)&S.csrsrc, g_csrsrc);
    cudaGetSymbolAddress((void**)&S.read,   g_read);

    cudaMemsetAsync(S.read, 0, sizeof(float) * 32 * 256, 0);

    run_branch(S, x_lig, src_lig, dst_lig, gid_lig,
               W1l, al1l, ar1l, b1l, W2l, al2l, ar2l, b2l, N_l, E_l, 0);
    run_branch(S, x_rec, src_rec, dst_rec, gid_rec,
               W1r, al1r, ar1r, b1r, W2r, al2r, ar2r, b2r, N_r, E_r, 128);

    mlp_kernel<<<1, 128>>>(S.read, W_lin1, b_lin1, W_lin2, b_lin2, (float*)d_out);
}